// round 6
// baseline (speedup 1.0000x reference)
#include <cuda_runtime.h>
#include <math.h>

#define BATCH   4096
#define NBLK    66
#define XDIM    264      // 66 * 4
#define PHI_H   256
#define PHI_OUT 64
#define RHO_H   256
#define WARPS_PER_BLOCK 4
#define NBLOCKS (BATCH / WARPS_PER_BLOCK)   // 1024

typedef unsigned long long ull;

// Global scratch: cross-batch max key + completion counter (self-resetting).
__device__ unsigned g_maxkey = 0u;
__device__ unsigned g_done   = 0u;

// ---- packed f32x2 helpers ----
__device__ __forceinline__ ull ffma2(ull a, ull b, ull c) {
    ull d; asm("fma.rn.f32x2 %0, %1, %2, %3;" : "=l"(d) : "l"(a), "l"(b), "l"(c)); return d;
}
__device__ __forceinline__ ull add2(ull a, ull b) {
    ull d; asm("add.rn.f32x2 %0, %1, %2;" : "=l"(d) : "l"(a), "l"(b)); return d;
}
__device__ __forceinline__ ull pack2(float lo, float hi) {
    ull v; asm("mov.b64 %0, {%1, %2};" : "=l"(v) : "f"(lo), "f"(hi)); return v;
}
__device__ __forceinline__ float2 unpack2(ull v) {
    float2 r; asm("mov.b64 {%0, %1}, %2;" : "=f"(r.x), "=f"(r.y) : "l"(v)); return r;
}
__device__ __forceinline__ ull dup2(float v) { return pack2(v, v); }

// Monotonic float->uint key.
__device__ __forceinline__ unsigned fkey(float f) {
    unsigned b = __float_as_uint(f);
    return (b & 0x80000000u) ? ~b : (b | 0x80000000u);
}
__device__ __forceinline__ float kinv(unsigned k) {
    unsigned b = (k & 0x80000000u) ? (k & 0x7fffffffu) : ~k;
    return __uint_as_float(b);
}

__global__ __launch_bounds__(32 * WARPS_PER_BLOCK, 7) void bn_main_kernel(
    const float* __restrict__ x,
    const float* __restrict__ pw1, const float* __restrict__ pb1,
    const float* __restrict__ pw2, const float* __restrict__ pb2,
    const float* __restrict__ rw1, const float* __restrict__ rb1,
    const float* __restrict__ rw2, const float* __restrict__ rb2,
    float* __restrict__ out)
{
    __shared__ __align__(16) float xs[WARPS_PER_BLOCK][XDIM];
    __shared__ __align__(16) float Hs[WARPS_PER_BLOCK][PHI_H];
    __shared__ __align__(16) float Xs[WARPS_PER_BLOCK][PHI_OUT];
    __shared__ unsigned s_max;
    __shared__ bool     s_last;

    const int tid  = threadIdx.x;
    const int w    = tid >> 5;
    const int lane = tid & 31;
    if (tid == 0) s_max = 0u;

    const int b = blockIdx.x * WARPS_PER_BLOCK + w;   // one batch row per warp

    // ---- stage x row into shared (coalesced float4) ----
    const float4* xrow4 = reinterpret_cast<const float4*>(x + (size_t)b * XDIM);
    float4* xs4 = reinterpret_cast<float4*>(xs[w]);
    for (int n = lane; n < NBLK; n += 32) xs4[n] = xrow4[n];
    __syncwarp();

    // ---- preload layer-1 weights packed over unit pairs:
    //      pair k2 covers units (lane + 64*k2, lane + 64*k2 + 32) ----
    ull w1p[4][4], b1p[4];
    #pragma unroll
    for (int k2 = 0; k2 < 4; k2++) {
        const int ja = lane + 64 * k2;
        const int jb = ja + 32;
        b1p[k2] = pack2(__ldg(pb1 + ja), __ldg(pb1 + jb));
        #pragma unroll
        for (int r = 0; r < 4; r++)
            w1p[r][k2] = pack2(__ldg(pw1 + r * PHI_H + ja), __ldg(pw1 + r * PHI_H + jb));
    }

    // ---- layer 1 + block-sum (packed over unit pairs) ----
    ull H2[4];
    #pragma unroll
    for (int k2 = 0; k2 < 4; k2++) H2[k2] = 0ull;

    #pragma unroll 2
    for (int n = 0; n < NBLK; n++) {
        const float4 s = xs4[n];
        const ull sx = dup2(s.x), sy = dup2(s.y), sz = dup2(s.z), sw = dup2(s.w);
        #pragma unroll
        for (int k2 = 0; k2 < 4; k2++) {
            ull t = ffma2(w1p[0][k2], sx, b1p[k2]);
            t = ffma2(w1p[1][k2], sy, t);
            t = ffma2(w1p[2][k2], sz, t);
            t = ffma2(w1p[3][k2], sw, t);
            const float2 u = unpack2(t);
            H2[k2] = add2(H2[k2], pack2(fmaxf(u.x, 0.f), fmaxf(u.y, 0.f)));
        }
    }
    #pragma unroll
    for (int k2 = 0; k2 < 4; k2++) {
        const float2 u = unpack2(H2[k2]);
        Hs[w][lane + 64 * k2]      = u.x;
        Hs[w][lane + 64 * k2 + 32] = u.y;
    }
    __syncwarp();

    // ---- X = H @ W2 + 66*b2 ; lane owns cols (2*lane, 2*lane+1), packed;
    //      4 independent accumulator chains ----
    {
        const float4* hv4 = reinterpret_cast<const float4*>(Hs[w]);
        const int c0 = 2 * lane;
        ull acc0 = 0ull, acc1 = 0ull, acc2 = 0ull, acc3 = 0ull;
        #pragma unroll 4
        for (int j4 = 0; j4 < PHI_H / 4; j4++) {
            const float4 h = hv4[j4];
            const int j = 4 * j4;
            const float2 v0 = __ldg(reinterpret_cast<const float2*>(pw2 + (j    ) * PHI_OUT + c0));
            const float2 v1 = __ldg(reinterpret_cast<const float2*>(pw2 + (j + 1) * PHI_OUT + c0));
            const float2 v2 = __ldg(reinterpret_cast<const float2*>(pw2 + (j + 2) * PHI_OUT + c0));
            const float2 v3 = __ldg(reinterpret_cast<const float2*>(pw2 + (j + 3) * PHI_OUT + c0));
            acc0 = ffma2(dup2(h.x), pack2(v0.x, v0.y), acc0);
            acc1 = ffma2(dup2(h.y), pack2(v1.x, v1.y), acc1);
            acc2 = ffma2(dup2(h.z), pack2(v2.x, v2.y), acc2);
            acc3 = ffma2(dup2(h.w), pack2(v3.x, v3.y), acc3);
        }
        const ull accT = add2(add2(acc0, acc1), add2(acc2, acc3));
        const float2 bv = __ldg(reinterpret_cast<const float2*>(pb2 + c0));
        const float2 u = unpack2(accT);
        Xs[w][c0]     = u.x + 66.f * bv.x;
        Xs[w][c0 + 1] = u.y + 66.f * bv.y;
    }
    __syncwarp();

    // ---- rho layer 1: lane owns 8 consecutive units (4 packed pairs);
    //      Xs fetched via LDS.128 once per 4 iterations ----
    const int j0 = 8 * lane;
    ull t0, t1, t2, t3;
    {
        const ulonglong2 ra = __ldg(reinterpret_cast<const ulonglong2*>(rb1 + j0));
        const ulonglong2 rb = __ldg(reinterpret_cast<const ulonglong2*>(rb1 + j0 + 4));
        t0 = ra.x; t1 = ra.y; t2 = rb.x; t3 = rb.y;
    }
    {
        const float4* Xv4 = reinterpret_cast<const float4*>(Xs[w]);
        #pragma unroll 4
        for (int i4 = 0; i4 < PHI_OUT / 4; i4++) {
            const float4 xv = Xv4[i4];
            const int i = 4 * i4;
            #pragma unroll
            for (int q = 0; q < 4; q++) {
                const float xi_s = (q == 0) ? xv.x : (q == 1) ? xv.y : (q == 2) ? xv.z : xv.w;
                const ull xi = dup2(xi_s);
                const ulonglong2 wa = __ldg(reinterpret_cast<const ulonglong2*>(rw1 + (i + q) * RHO_H + j0));
                const ulonglong2 wb = __ldg(reinterpret_cast<const ulonglong2*>(rw1 + (i + q) * RHO_H + j0 + 4));
                t0 = ffma2(xi, wa.x, t0);  t1 = ffma2(xi, wa.y, t1);
                t2 = ffma2(xi, wb.x, t2);  t3 = ffma2(xi, wb.y, t3);
            }
        }
    }

    // ---- relu + rho layer 2 (rw2 rows j0..j0+7), packed (a0,a1) ----
    ull a2 = 0ull;
    {
        const float4 r0 = __ldg(reinterpret_cast<const float4*>(rw2 + 2 * j0));
        const float4 r1 = __ldg(reinterpret_cast<const float4*>(rw2 + 2 * j0 + 4));
        const float4 r2 = __ldg(reinterpret_cast<const float4*>(rw2 + 2 * j0 + 8));
        const float4 r3 = __ldg(reinterpret_cast<const float4*>(rw2 + 2 * j0 + 12));
        const float2 u0 = unpack2(t0), u1 = unpack2(t1);
        const float2 u2 = unpack2(t2), u3 = unpack2(t3);
        a2 = ffma2(dup2(fmaxf(u0.x, 0.f)), pack2(r0.x, r0.y), a2);
        a2 = ffma2(dup2(fmaxf(u0.y, 0.f)), pack2(r0.z, r0.w), a2);
        a2 = ffma2(dup2(fmaxf(u1.x, 0.f)), pack2(r1.x, r1.y), a2);
        a2 = ffma2(dup2(fmaxf(u1.y, 0.f)), pack2(r1.z, r1.w), a2);
        a2 = ffma2(dup2(fmaxf(u2.x, 0.f)), pack2(r2.x, r2.y), a2);
        a2 = ffma2(dup2(fmaxf(u2.y, 0.f)), pack2(r2.z, r2.w), a2);
        a2 = ffma2(dup2(fmaxf(u3.x, 0.f)), pack2(r3.x, r3.y), a2);
        a2 = ffma2(dup2(fmaxf(u3.y, 0.f)), pack2(r3.z, r3.w), a2);
    }

    // ---- barrier term over neighbors n = 2..65 (2 per lane) ----
    float bx = 0.f, by = 0.f;
    #pragma unroll
    for (int q = 0; q < 2; q++) {
        const int n = 2 + lane + 32 * q;
        const float px = xs[w][4 * n], py = xs[w][4 * n + 1];
        const float dm = sqrtf(px * px + py * py) - 0.15f;
        const float inv = 1.f / (dm * dm);
        bx -= px * inv;
        by -= py * inv;
    }

    // ---- warp butterfly reduce (a0, a1, bx, by) ----
    float a0, a1;
    { const float2 u = unpack2(a2); a0 = u.x; a1 = u.y; }
    #pragma unroll
    for (int off = 16; off > 0; off >>= 1) {
        a0 += __shfl_xor_sync(0xffffffff, a0, off);
        a1 += __shfl_xor_sync(0xffffffff, a1, off);
        bx += __shfl_xor_sync(0xffffffff, bx, off);
        by += __shfl_xor_sync(0xffffffff, by, off);
    }

    __syncthreads();  // orders s_max init before atomics below
    if (lane == 0) {
        const float r0 = 2.0f * tanhf(a0 + __ldg(rb2))     + bx;
        const float r1 = 2.0f * tanhf(a1 + __ldg(rb2 + 1)) + by;
        out[2 * b]     = r0;
        out[2 * b + 1] = r1;
        const unsigned k = max(fkey(r0), fkey(r1));
        atomicMax(&s_max, k);
    }
    __syncthreads();

    // ---- block max -> global; last block applies global rescale ----
    if (tid == 0) {
        atomicMax(&g_maxkey, s_max);
        __threadfence();
        const unsigned prev = atomicAdd(&g_done, 1u);
        s_last = (prev == (unsigned)(gridDim.x - 1));
    }
    __syncthreads();

    if (s_last) {
        __threadfence();
        const float mx    = kinv(atomicAdd(&g_maxkey, 0u));
        const float scale = 2.0f / mx;
        if (scale < 1.0f) {
            float4* o4 = reinterpret_cast<float4*>(out);
            for (int i = tid; i < BATCH * 2 / 4; i += blockDim.x) {
                float4 v = o4[i];
                v.x *= scale; v.y *= scale; v.z *= scale; v.w *= scale;
                o4[i] = v;
            }
        }
        __syncthreads();
        if (tid == 0) {
            g_maxkey = 0u;
            __threadfence();
            atomicExch(&g_done, 0u);
        }
    }
}

extern "C" void kernel_launch(void* const* d_in, const int* in_sizes, int n_in,
                              void* d_out, int out_size)
{
    const float* x   = (const float*)d_in[0];
    const float* pw1 = (const float*)d_in[1];
    const float* pb1 = (const float*)d_in[2];
    const float* pw2 = (const float*)d_in[3];
    const float* pb2 = (const float*)d_in[4];
    const float* rw1 = (const float*)d_in[5];
    const float* rb1 = (const float*)d_in[6];
    const float* rw2 = (const float*)d_in[7];
    const float* rb2 = (const float*)d_in[8];
    float* out = (float*)d_out;

    bn_main_kernel<<<NBLOCKS, 32 * WARPS_PER_BLOCK>>>(
        x, pw1, pb1, pw2, pb2, rw1, rb1, rw2, rb2, out);
}

// round 11
// speedup vs baseline: 1.0993x; 1.0993x over previous
#include <cuda_runtime.h>
#include <math.h>

#define BATCH   4096
#define NBLK    66
#define XDIM    264      // 66 * 4
#define PHI_H   256
#define PHI_OUT 64
#define RHO_H   256
#define WARPS_PER_BLOCK 2
#define ROWS_PER_WARP   2
#define ROWS_PER_BLOCK  (WARPS_PER_BLOCK * ROWS_PER_WARP)   // 4
#define NBLOCKS (BATCH / ROWS_PER_BLOCK)                    // 1024

typedef unsigned long long ull;

// Global scratch: cross-batch max key + completion counter (self-resetting).
__device__ unsigned g_maxkey = 0u;
__device__ unsigned g_done   = 0u;

// ---- packed f32x2 helpers ----
__device__ __forceinline__ ull ffma2(ull a, ull b, ull c) {
    ull d; asm("fma.rn.f32x2 %0, %1, %2, %3;" : "=l"(d) : "l"(a), "l"(b), "l"(c)); return d;
}
__device__ __forceinline__ ull add2(ull a, ull b) {
    ull d; asm("add.rn.f32x2 %0, %1, %2;" : "=l"(d) : "l"(a), "l"(b)); return d;
}
__device__ __forceinline__ ull pack2(float lo, float hi) {
    ull v; asm("mov.b64 %0, {%1, %2};" : "=l"(v) : "f"(lo), "f"(hi)); return v;
}
__device__ __forceinline__ float2 unpack2(ull v) {
    float2 r; asm("mov.b64 {%0, %1}, %2;" : "=f"(r.x), "=f"(r.y) : "l"(v)); return r;
}
__device__ __forceinline__ ull dup2(float v) { return pack2(v, v); }

// Monotonic float->uint key.
__device__ __forceinline__ unsigned fkey(float f) {
    unsigned b = __float_as_uint(f);
    return (b & 0x80000000u) ? ~b : (b | 0x80000000u);
}
__device__ __forceinline__ float kinv(unsigned k) {
    unsigned b = (k & 0x80000000u) ? (k & 0x7fffffffu) : ~k;
    return __uint_as_float(b);
}

__global__ __launch_bounds__(32 * WARPS_PER_BLOCK, 8) void bn_main_kernel(
    const float* __restrict__ x,
    const float* __restrict__ pw1, const float* __restrict__ pb1,
    const float* __restrict__ pw2, const float* __restrict__ pb2,
    const float* __restrict__ rw1, const float* __restrict__ rb1,
    const float* __restrict__ rw2, const float* __restrict__ rb2,
    float* __restrict__ out)
{
    __shared__ __align__(16) float xs[WARPS_PER_BLOCK][ROWS_PER_WARP][XDIM];
    __shared__ __align__(16) float Hs[WARPS_PER_BLOCK][ROWS_PER_WARP][PHI_H];
    __shared__ __align__(16) float Xs[WARPS_PER_BLOCK][ROWS_PER_WARP][PHI_OUT];
    __shared__ unsigned s_max;
    __shared__ bool     s_last;

    const int tid  = threadIdx.x;
    const int w    = tid >> 5;
    const int lane = tid & 31;
    if (tid == 0) s_max = 0u;

    const int bA = blockIdx.x * ROWS_PER_BLOCK + w * ROWS_PER_WARP;  // row A
    const int bB = bA + 1;                                           // row B

    // ---- stage both x rows into shared (coalesced float4) ----
    {
        const float4* rA = reinterpret_cast<const float4*>(x + (size_t)bA * XDIM);
        const float4* rB = reinterpret_cast<const float4*>(x + (size_t)bB * XDIM);
        float4* sA = reinterpret_cast<float4*>(xs[w][0]);
        float4* sB = reinterpret_cast<float4*>(xs[w][1]);
        for (int n = lane; n < NBLK; n += 32) { sA[n] = rA[n]; sB[n] = rB[n]; }
    }
    __syncwarp();

    // ---- preload layer-1 weights packed over unit pairs:
    //      pair k2 covers units (lane + 64*k2, lane + 64*k2 + 32) ----
    ull w1p[4][4], b1p[4];
    #pragma unroll
    for (int k2 = 0; k2 < 4; k2++) {
        const int ja = lane + 64 * k2;
        const int jb = ja + 32;
        b1p[k2] = pack2(__ldg(pb1 + ja), __ldg(pb1 + jb));
        #pragma unroll
        for (int r = 0; r < 4; r++)
            w1p[r][k2] = pack2(__ldg(pw1 + r * PHI_H + ja), __ldg(pw1 + r * PHI_H + jb));
    }

    // ---- layer 1 + block-sum, BOTH rows interleaved (8 parallel FFMA2 chains) ----
    ull HA[4], HB[4];
    #pragma unroll
    for (int k2 = 0; k2 < 4; k2++) { HA[k2] = 0ull; HB[k2] = 0ull; }

    {
        const float4* sA4 = reinterpret_cast<const float4*>(xs[w][0]);
        const float4* sB4 = reinterpret_cast<const float4*>(xs[w][1]);
        #pragma unroll 2
        for (int n = 0; n < NBLK; n++) {
            const float4 sa = sA4[n];
            const float4 sb = sB4[n];
            const ull ax = dup2(sa.x), ay = dup2(sa.y), az = dup2(sa.z), aw = dup2(sa.w);
            const ull bx2 = dup2(sb.x), by2 = dup2(sb.y), bz2 = dup2(sb.z), bw2 = dup2(sb.w);
            #pragma unroll
            for (int k2 = 0; k2 < 4; k2++) {
                ull tA = ffma2(w1p[0][k2], ax, b1p[k2]);
                ull tB = ffma2(w1p[0][k2], bx2, b1p[k2]);
                tA = ffma2(w1p[1][k2], ay, tA);
                tB = ffma2(w1p[1][k2], by2, tB);
                tA = ffma2(w1p[2][k2], az, tA);
                tB = ffma2(w1p[2][k2], bz2, tB);
                tA = ffma2(w1p[3][k2], aw, tA);
                tB = ffma2(w1p[3][k2], bw2, tB);
                const float2 uA = unpack2(tA);
                const float2 uB = unpack2(tB);
                HA[k2] = add2(HA[k2], pack2(fmaxf(uA.x, 0.f), fmaxf(uA.y, 0.f)));
                HB[k2] = add2(HB[k2], pack2(fmaxf(uB.x, 0.f), fmaxf(uB.y, 0.f)));
            }
        }
    }
    #pragma unroll
    for (int k2 = 0; k2 < 4; k2++) {
        const float2 uA = unpack2(HA[k2]);
        const float2 uB = unpack2(HB[k2]);
        Hs[w][0][lane + 64 * k2]      = uA.x;
        Hs[w][0][lane + 64 * k2 + 32] = uA.y;
        Hs[w][1][lane + 64 * k2]      = uB.x;
        Hs[w][1][lane + 64 * k2 + 32] = uB.y;
    }
    __syncwarp();

    // ---- X = H @ W2 + 66*b2 ; lane owns packed cols (2*lane, 2*lane+1);
    //      weight rows loaded once as ull, shared across both rows ----
    {
        const float4* hA4 = reinterpret_cast<const float4*>(Hs[w][0]);
        const float4* hB4 = reinterpret_cast<const float4*>(Hs[w][1]);
        const int c0 = 2 * lane;
        const char* pw2c = reinterpret_cast<const char*>(pw2 + c0);
        ull accA = 0ull, accB = 0ull;
        #pragma unroll 8
        for (int j4 = 0; j4 < PHI_H / 4; j4++) {
            const float4 hA = hA4[j4];
            const float4 hB = hB4[j4];
            const size_t base = (size_t)(4 * j4) * (PHI_OUT * 4);
            const ull w0 = __ldg(reinterpret_cast<const ull*>(pw2c + base));
            const ull w1 = __ldg(reinterpret_cast<const ull*>(pw2c + base + PHI_OUT * 4));
            const ull w2 = __ldg(reinterpret_cast<const ull*>(pw2c + base + PHI_OUT * 8));
            const ull w3 = __ldg(reinterpret_cast<const ull*>(pw2c + base + PHI_OUT * 12));
            accA = ffma2(dup2(hA.x), w0, accA);
            accB = ffma2(dup2(hB.x), w0, accB);
            accA = ffma2(dup2(hA.y), w1, accA);
            accB = ffma2(dup2(hB.y), w1, accB);
            accA = ffma2(dup2(hA.z), w2, accA);
            accB = ffma2(dup2(hB.z), w2, accB);
            accA = ffma2(dup2(hA.w), w3, accA);
            accB = ffma2(dup2(hB.w), w3, accB);
        }
        const float2 bv = __ldg(reinterpret_cast<const float2*>(pb2 + c0));
        const ull b66 = pack2(66.f * bv.x, 66.f * bv.y);
        const float2 uA = unpack2(add2(accA, b66));
        const float2 uB = unpack2(add2(accB, b66));
        Xs[w][0][c0]     = uA.x;
        Xs[w][0][c0 + 1] = uA.y;
        Xs[w][1][c0]     = uB.x;
        Xs[w][1][c0 + 1] = uB.y;
    }
    __syncwarp();

    // ---- rho layer 1: lane owns 8 consecutive units (4 packed pairs);
    //      weight loads shared across both rows ----
    const int j0 = 8 * lane;
    ull tA[4], tB[4];
    {
        const ulonglong2 ra = __ldg(reinterpret_cast<const ulonglong2*>(rb1 + j0));
        const ulonglong2 rb = __ldg(reinterpret_cast<const ulonglong2*>(rb1 + j0 + 4));
        tA[0] = ra.x; tA[1] = ra.y; tA[2] = rb.x; tA[3] = rb.y;
        tB[0] = ra.x; tB[1] = ra.y; tB[2] = rb.x; tB[3] = rb.y;
    }
    {
        const float4* XA4 = reinterpret_cast<const float4*>(Xs[w][0]);
        const float4* XB4 = reinterpret_cast<const float4*>(Xs[w][1]);
        #pragma unroll 4
        for (int i4 = 0; i4 < PHI_OUT / 4; i4++) {
            const float4 xa = XA4[i4];
            const float4 xb = XB4[i4];
            const int i = 4 * i4;
            #pragma unroll
            for (int q = 0; q < 4; q++) {
                const float xaq = (q == 0) ? xa.x : (q == 1) ? xa.y : (q == 2) ? xa.z : xa.w;
                const float xbq = (q == 0) ? xb.x : (q == 1) ? xb.y : (q == 2) ? xb.z : xb.w;
                const ull xA = dup2(xaq);
                const ull xB = dup2(xbq);
                const ulonglong2 wa = __ldg(reinterpret_cast<const ulonglong2*>(rw1 + (i + q) * RHO_H + j0));
                const ulonglong2 wb = __ldg(reinterpret_cast<const ulonglong2*>(rw1 + (i + q) * RHO_H + j0 + 4));
                tA[0] = ffma2(xA, wa.x, tA[0]);  tB[0] = ffma2(xB, wa.x, tB[0]);
                tA[1] = ffma2(xA, wa.y, tA[1]);  tB[1] = ffma2(xB, wa.y, tB[1]);
                tA[2] = ffma2(xA, wb.x, tA[2]);  tB[2] = ffma2(xB, wb.x, tB[2]);
                tA[3] = ffma2(xA, wb.y, tA[3]);  tB[3] = ffma2(xB, wb.y, tB[3]);
            }
        }
    }

    // ---- relu + rho layer 2 (rw2 rows j0..j0+7); loads shared; packed (a0,a1) ----
    ull aA2 = 0ull, aB2 = 0ull;
    {
        const ulonglong2 q01 = __ldg(reinterpret_cast<const ulonglong2*>(rw2 + 2 * j0));
        const ulonglong2 q23 = __ldg(reinterpret_cast<const ulonglong2*>(rw2 + 2 * j0 + 4));
        const ulonglong2 q45 = __ldg(reinterpret_cast<const ulonglong2*>(rw2 + 2 * j0 + 8));
        const ulonglong2 q67 = __ldg(reinterpret_cast<const ulonglong2*>(rw2 + 2 * j0 + 12));
        const float2 uA0 = unpack2(tA[0]), uA1 = unpack2(tA[1]);
        const float2 uA2 = unpack2(tA[2]), uA3 = unpack2(tA[3]);
        const float2 uB0 = unpack2(tB[0]), uB1 = unpack2(tB[1]);
        const float2 uB2 = unpack2(tB[2]), uB3 = unpack2(tB[3]);
        aA2 = ffma2(dup2(fmaxf(uA0.x, 0.f)), q01.x, aA2);
        aB2 = ffma2(dup2(fmaxf(uB0.x, 0.f)), q01.x, aB2);
        aA2 = ffma2(dup2(fmaxf(uA0.y, 0.f)), q01.y, aA2);
        aB2 = ffma2(dup2(fmaxf(uB0.y, 0.f)), q01.y, aB2);
        aA2 = ffma2(dup2(fmaxf(uA1.x, 0.f)), q23.x, aA2);
        aB2 = ffma2(dup2(fmaxf(uB1.x, 0.f)), q23.x, aB2);
        aA2 = ffma2(dup2(fmaxf(uA1.y, 0.f)), q23.y, aA2);
        aB2 = ffma2(dup2(fmaxf(uB1.y, 0.f)), q23.y, aB2);
        aA2 = ffma2(dup2(fmaxf(uA2.x, 0.f)), q45.x, aA2);
        aB2 = ffma2(dup2(fmaxf(uB2.x, 0.f)), q45.x, aB2);
        aA2 = ffma2(dup2(fmaxf(uA2.y, 0.f)), q45.y, aA2);
        aB2 = ffma2(dup2(fmaxf(uB2.y, 0.f)), q45.y, aB2);
        aA2 = ffma2(dup2(fmaxf(uA3.x, 0.f)), q67.x, aA2);
        aB2 = ffma2(dup2(fmaxf(uB3.x, 0.f)), q67.x, aB2);
        aA2 = ffma2(dup2(fmaxf(uA3.y, 0.f)), q67.y, aA2);
        aB2 = ffma2(dup2(fmaxf(uB3.y, 0.f)), q67.y, aB2);
    }

    // ---- barrier term over neighbors n = 2..65 (2 per lane per row) ----
    float bxA = 0.f, byA = 0.f, bxB = 0.f, byB = 0.f;
    #pragma unroll
    for (int q = 0; q < 2; q++) {
        const int n = 2 + lane + 32 * q;
        {
            const float px = xs[w][0][4 * n], py = xs[w][0][4 * n + 1];
            const float dm = sqrtf(px * px + py * py) - 0.15f;
            const float inv = 1.f / (dm * dm);
            bxA -= px * inv;  byA -= py * inv;
        }
        {
            const float px = xs[w][1][4 * n], py = xs[w][1][4 * n + 1];
            const float dm = sqrtf(px * px + py * py) - 0.15f;
            const float inv = 1.f / (dm * dm);
            bxB -= px * inv;  byB -= py * inv;
        }
    }

    // ---- warp butterfly reduce ----
    float a0A, a1A, a0B, a1B;
    { const float2 u = unpack2(aA2); a0A = u.x; a1A = u.y; }
    { const float2 u = unpack2(aB2); a0B = u.x; a1B = u.y; }
    #pragma unroll
    for (int off = 16; off > 0; off >>= 1) {
        a0A += __shfl_xor_sync(0xffffffff, a0A, off);
        a1A += __shfl_xor_sync(0xffffffff, a1A, off);
        a0B += __shfl_xor_sync(0xffffffff, a0B, off);
        a1B += __shfl_xor_sync(0xffffffff, a1B, off);
        bxA += __shfl_xor_sync(0xffffffff, bxA, off);
        byA += __shfl_xor_sync(0xffffffff, byA, off);
        bxB += __shfl_xor_sync(0xffffffff, bxB, off);
        byB += __shfl_xor_sync(0xffffffff, byB, off);
    }

    __syncthreads();  // orders s_max init before atomics below
    if (lane == 0) {
        const float rb20 = __ldg(rb2), rb21 = __ldg(rb2 + 1);
        const float rA0 = 2.0f * tanhf(a0A + rb20) + bxA;
        const float rA1 = 2.0f * tanhf(a1A + rb21) + byA;
        const float rB0 = 2.0f * tanhf(a0B + rb20) + bxB;
        const float rB1 = 2.0f * tanhf(a1B + rb21) + byB;
        out[2 * bA]     = rA0;
        out[2 * bA + 1] = rA1;
        out[2 * bB]     = rB0;
        out[2 * bB + 1] = rB1;
        const unsigned k = max(max(fkey(rA0), fkey(rA1)), max(fkey(rB0), fkey(rB1)));
        atomicMax(&s_max, k);
    }
    __syncthreads();

    // ---- block max -> global; last block applies global rescale ----
    if (tid == 0) {
        atomicMax(&g_maxkey, s_max);
        __threadfence();
        const unsigned prev = atomicAdd(&g_done, 1u);
        s_last = (prev == (unsigned)(gridDim.x - 1));
    }
    __syncthreads();

    if (s_last) {
        __threadfence();
        const float mx    = kinv(atomicAdd(&g_maxkey, 0u));
        const float scale = 2.0f / mx;
        if (scale < 1.0f) {
            float4* o4 = reinterpret_cast<float4*>(out);
            for (int i = tid; i < BATCH * 2 / 4; i += blockDim.x) {
                float4 v = o4[i];
                v.x *= scale; v.y *= scale; v.z *= scale; v.w *= scale;
                o4[i] = v;
            }
        }
        __syncthreads();
        if (tid == 0) {
            g_maxkey = 0u;
            __threadfence();
            atomicExch(&g_done, 0u);
        }
    }
}

extern "C" void kernel_launch(void* const* d_in, const int* in_sizes, int n_in,
                              void* d_out, int out_size)
{
    const float* x   = (const float*)d_in[0];
    const float* pw1 = (const float*)d_in[1];
    const float* pb1 = (const float*)d_in[2];
    const float* pw2 = (const float*)d_in[3];
    const float* pb2 = (const float*)d_in[4];
    const float* rw1 = (const float*)d_in[5];
    const float* rb1 = (const float*)d_in[6];
    const float* rw2 = (const float*)d_in[7];
    const float* rb2 = (const float*)d_in[8];
    float* out = (float*)d_out;

    bn_main_kernel<<<NBLOCKS, 32 * WARPS_PER_BLOCK>>>(
        x, pw1, pb1, pw2, pb2, rw1, rb1, rw2, rb2, out);
}